// round 9
// baseline (speedup 1.0000x reference)
#include <cuda_runtime.h>
#include <cuda_fp16.h>
#include <cstdint>

#define FD 128          // feature dim (in == out == 128)
#define NMAX 100000
#define EMAX 1600000

#define WFIX 1048576.0f           // 2^20 fixed-point scale for edge weights
#define ACC_MASK ((1ULL << 40) - 1ULL)

// ---------------- scratch (static device globals; no allocation allowed) ----
__device__ __half g_h[(size_t)NMAX * FD];           // x @ W (fp16 store)
__device__ unsigned long long g_acc[NMAX];          // (count<<40)|fixed20(sum w); 0 by invariant
__device__ float g_dinv[NMAX];                      // rsqrt(deg)
__device__ int   g_start[NMAX];                     // CSR segment start
__device__ int   g_end[NMAX];                       // CSR segment end
__device__ unsigned short g_rank[EMAX];             // edge's rank within dst segment
__device__ uint2 g_edge[EMAX];                      // CSR: packed (src, norm)
__device__ unsigned int g_total;                    // arrival-ordered base; 0 by invariant
__device__ unsigned int g_done;                     // block-done counter; 0 by invariant

// ---------------- pass 1: degree+histogram; atomic return gives edge rank --
__global__ void k_deg(const int* __restrict__ dst, const float* __restrict__ w,
                      int e) {
    int i = (blockIdx.x * blockDim.x + threadIdx.x) * 4;
    if (i + 4 <= e) {
        int4   d  = __ldcs((const int4*)&dst[i]);     // streamed: read once
        float4 ww = __ldcs((const float4*)&w[i]);
        unsigned long long o0 = atomicAdd(&g_acc[d.x],
            (1ULL << 40) | (unsigned long long)(ww.x * WFIX + 0.5f));
        unsigned long long o1 = atomicAdd(&g_acc[d.y],
            (1ULL << 40) | (unsigned long long)(ww.y * WFIX + 0.5f));
        unsigned long long o2 = atomicAdd(&g_acc[d.z],
            (1ULL << 40) | (unsigned long long)(ww.z * WFIX + 0.5f));
        unsigned long long o3 = atomicAdd(&g_acc[d.w],
            (1ULL << 40) | (unsigned long long)(ww.w * WFIX + 0.5f));
        ushort4 r = make_ushort4((unsigned short)(o0 >> 40),
                                 (unsigned short)(o1 >> 40),
                                 (unsigned short)(o2 >> 40),
                                 (unsigned short)(o3 >> 40));
        *(ushort4*)&g_rank[i] = r;                    // coalesced 8B store
    } else {
        for (int j = i; j < e; j++) {
            unsigned long long o = atomicAdd(&g_acc[dst[j]],
                (1ULL << 40) | (unsigned long long)(w[j] * WFIX + 0.5f));
            g_rank[j] = (unsigned short)(o >> 40);
        }
    }
}

// ---------------- single-kernel scan: dinv + arrival-ordered CSR offsets ---
__global__ void __launch_bounds__(1024) k_scan(int n, int nb) {
    __shared__ int ws[32];
    __shared__ int s_base;
    int tid = threadIdx.x;
    int i = blockIdx.x * 1024 + tid;
    int c = 0;
    if (i < n) {
        unsigned long long a = g_acc[i];
        c = (int)(a >> 40);
        float deg = (float)(a & ACC_MASK) * (1.0f / WFIX) + 1.0f;   // +1 self-loop
        g_dinv[i] = rsqrtf(deg);
        g_acc[i] = 0ULL;                 // restore invariant for next replay
    }
    int lane = tid & 31, wid = tid >> 5;
    int inc = c;
    #pragma unroll
    for (int o = 1; o < 32; o <<= 1) {
        int t = __shfl_up_sync(0xFFFFFFFFu, inc, o);
        if (lane >= o) inc += t;
    }
    if (lane == 31) ws[wid] = inc;
    __syncthreads();
    if (wid == 0) {
        int v = ws[lane];
        #pragma unroll
        for (int o = 1; o < 32; o <<= 1) {
            int t = __shfl_up_sync(0xFFFFFFFFu, v, o);
            if (lane >= o) v += t;
        }
        ws[lane] = v;
    }
    __syncthreads();
    int incl = ((wid > 0) ? ws[wid - 1] : 0) + inc;   // block-inclusive
    if (tid == 1023)
        s_base = (int)atomicAdd(&g_total, (unsigned)incl);
    __syncthreads();
    if (i < n) {
        int start = s_base + incl - c;
        g_start[i] = start;
        g_end[i]   = start + c;
    }
    __syncthreads();
    if (tid == 0 && atomicAdd(&g_done, 1u) == (unsigned)(nb - 1)) {
        g_total = 0u;                    // self-clean for next replay
        g_done  = 0u;
    }
}

// ---------------- pass 2: place packed (src,norm); NO atomics --------------
__global__ void k_place(const int* __restrict__ src, const int* __restrict__ dst,
                        const float* __restrict__ w, int e) {
    int i = (blockIdx.x * blockDim.x + threadIdx.x) * 4;
    if (i + 4 <= e) {
        int4    s4 = __ldcs((const int4*)&src[i]);
        int4    d4 = __ldcs((const int4*)&dst[i]);
        float4  w4 = __ldcs((const float4*)&w[i]);
        ushort4 r4 = *(const ushort4*)&g_rank[i];
        // gather all random-but-L2-resident scalars up front (high MLP)
        float ds0 = g_dinv[s4.x], dd0 = g_dinv[d4.x];
        float ds1 = g_dinv[s4.y], dd1 = g_dinv[d4.y];
        float ds2 = g_dinv[s4.z], dd2 = g_dinv[d4.z];
        float ds3 = g_dinv[s4.w], dd3 = g_dinv[d4.w];
        int p0 = g_start[d4.x] + r4.x;
        int p1 = g_start[d4.y] + r4.y;
        int p2 = g_start[d4.z] + r4.z;
        int p3 = g_start[d4.w] + r4.w;
        g_edge[p0] = make_uint2((uint32_t)s4.x, __float_as_uint(ds0 * w4.x * dd0));
        g_edge[p1] = make_uint2((uint32_t)s4.y, __float_as_uint(ds1 * w4.y * dd1));
        g_edge[p2] = make_uint2((uint32_t)s4.z, __float_as_uint(ds2 * w4.z * dd2));
        g_edge[p3] = make_uint2((uint32_t)s4.w, __float_as_uint(ds3 * w4.w * dd3));
    } else {
        for (int j = i; j < e; j++) {
            int s = src[j], d = dst[j];
            float nw = g_dinv[s] * w[j] * g_dinv[d];
            int pos = g_start[d] + g_rank[j];
            g_edge[pos] = make_uint2((uint32_t)s, __float_as_uint(nw));
        }
    }
}

// ---------------- GEMM: h = x @ W via TF32 mma.sync, fp16 output -----------
__device__ __forceinline__ uint32_t f2tf32(float f) {
    uint32_t r;
    asm("cvt.rna.tf32.f32 %0, %1;" : "=r"(r) : "f"(f));
    return r;
}

#define BM  64
#define KCH 32
#define AST 36
#define WST 136

__global__ void __launch_bounds__(256) k_gemm(const float* __restrict__ x,
                                              const float* __restrict__ W, int n) {
    __shared__ uint32_t As[BM * AST];
    __shared__ uint32_t Ws[KCH * WST];
    int tid = threadIdx.x;
    int lane = tid & 31, wid = tid >> 5;
    int warpM = wid & 3, warpN = wid >> 2;
    int row0 = blockIdx.x * BM;
    int qr = lane >> 2;
    int qk = lane & 3;

    float c[8][4];
    #pragma unroll
    for (int t = 0; t < 8; t++)
        #pragma unroll
        for (int j = 0; j < 4; j++) c[t][j] = 0.0f;

    for (int kc = 0; kc < FD; kc += KCH) {
        __syncthreads();
        #pragma unroll
        for (int i = tid; i < BM * KCH; i += 256) {
            int r = i >> 5, k = i & 31;
            int gr = row0 + r;
            float v = (gr < n) ? x[(size_t)gr * FD + kc + k] : 0.0f;
            As[r * AST + k] = f2tf32(v);
        }
        #pragma unroll
        for (int i = tid; i < KCH * FD; i += 256) {
            int k = i >> 7, nn = i & 127;
            Ws[k * WST + nn] = f2tf32(W[(size_t)(kc + k) * FD + nn]);
        }
        __syncthreads();

        #pragma unroll
        for (int kk = 0; kk < KCH; kk += 8) {
            int ar = warpM * 16 + qr;
            uint32_t a0 = As[ar * AST + kk + qk];
            uint32_t a1 = As[(ar + 8) * AST + kk + qk];
            uint32_t a2 = As[ar * AST + kk + qk + 4];
            uint32_t a3 = As[(ar + 8) * AST + kk + qk + 4];
            #pragma unroll
            for (int t = 0; t < 8; t++) {
                int bn = warpN * 64 + t * 8 + qr;
                uint32_t b0 = Ws[(kk + qk) * WST + bn];
                uint32_t b1 = Ws[(kk + qk + 4) * WST + bn];
                asm volatile(
                    "mma.sync.aligned.m16n8k8.row.col.f32.tf32.tf32.f32 "
                    "{%0,%1,%2,%3}, {%4,%5,%6,%7}, {%8,%9}, {%0,%1,%2,%3};"
                    : "+f"(c[t][0]), "+f"(c[t][1]), "+f"(c[t][2]), "+f"(c[t][3])
                    : "r"(a0), "r"(a1), "r"(a2), "r"(a3), "r"(b0), "r"(b1));
            }
        }
    }

    int mr = row0 + warpM * 16 + qr;
    #pragma unroll
    for (int t = 0; t < 8; t++) {
        int col = warpN * 64 + t * 8 + 2 * qk;
        if (mr < n)
            *(__half2*)&g_h[(size_t)mr * FD + col] = __floats2half2_rn(c[t][0], c[t][1]);
        if (mr + 8 < n)
            *(__half2*)&g_h[(size_t)(mr + 8) * FD + col] = __floats2half2_rn(c[t][2], c[t][3]);
    }
}

// ---------------- gather: one warp per dst node, MLP-8 inner loop ----------
__device__ __forceinline__ void fma_row(float4& acc, uint2 raw, float nw) {
    __half2 h0 = *reinterpret_cast<__half2*>(&raw.x);
    __half2 h1 = *reinterpret_cast<__half2*>(&raw.y);
    float2 f0 = __half22float2(h0), f1 = __half22float2(h1);
    acc.x += f0.x * nw; acc.y += f0.y * nw;
    acc.z += f1.x * nw; acc.w += f1.y * nw;
}

__device__ __forceinline__ void stream_f4(float* p, float4 v) {
    asm volatile("st.global.cs.v4.f32 [%0], {%1,%2,%3,%4};"
                 :: "l"(p), "f"(v.x), "f"(v.y), "f"(v.z), "f"(v.w) : "memory");
}

__global__ void __launch_bounds__(256) k_gather(const float* __restrict__ b,
                                                float* __restrict__ out, int n) {
    int warp = (blockIdx.x * blockDim.x + threadIdx.x) >> 5;
    int lane = threadIdx.x & 31;
    if (warp >= n) return;
    int beg = g_start[warp];
    int end = g_end[warp];
    float4 acc = make_float4(0.f, 0.f, 0.f, 0.f);
    size_t loff = (size_t)lane * 4;

    int e = beg;
    for (; e + 8 <= end; e += 8) {
        uint2 p[8], r[8];
        #pragma unroll
        for (int j = 0; j < 8; j++) p[j] = __ldcs(&g_edge[e + j]);   // streamed
        #pragma unroll
        for (int j = 0; j < 8; j++)
            r[j] = *(const uint2*)&g_h[(size_t)p[j].x * FD + loff];
        #pragma unroll
        for (int j = 0; j < 8; j++)
            fma_row(acc, r[j], __uint_as_float(p[j].y));
    }
    for (; e + 2 <= end; e += 2) {
        uint2 p0 = __ldcs(&g_edge[e]), p1 = __ldcs(&g_edge[e + 1]);
        uint2 r0 = *(const uint2*)&g_h[(size_t)p0.x * FD + loff];
        uint2 r1 = *(const uint2*)&g_h[(size_t)p1.x * FD + loff];
        fma_row(acc, r0, __uint_as_float(p0.y));
        fma_row(acc, r1, __uint_as_float(p1.y));
    }
    if (e < end) {
        uint2 p = __ldcs(&g_edge[e]);
        uint2 r = *(const uint2*)&g_h[(size_t)p.x * FD + loff];
        fma_row(acc, r, __uint_as_float(p.y));
    }

    // self-loop: norm = dinv^2, then + bias
    float di = g_dinv[warp];
    uint2 raw = *(const uint2*)&g_h[(size_t)warp * FD + loff];
    fma_row(acc, raw, di * di);
    float4 bv = *(const float4*)&b[lane * 4];
    acc.x += bv.x; acc.y += bv.y; acc.z += bv.z; acc.w += bv.w;

    size_t off = (size_t)warp * FD + loff;
    stream_f4(&out[off], acc);
    float4 rv = make_float4(fmaxf(acc.x, 0.f), fmaxf(acc.y, 0.f),
                            fmaxf(acc.z, 0.f), fmaxf(acc.w, 0.f));
    stream_f4(&out[(size_t)n * FD + off], rv);
}

// ---------------- launcher -------------------------------------------------
static cudaStream_t g_s2 = nullptr;
static cudaEvent_t  g_evFork = nullptr, g_evJoin = nullptr;

extern "C" void kernel_launch(void* const* d_in, const int* in_sizes, int n_in,
                              void* d_out, int out_size) {
    (void)n_in; (void)out_size;
    const float* x  = (const float*)d_in[0];
    const float* W  = (const float*)d_in[1];
    const float* b  = (const float*)d_in[2];
    // d_in[3] = level (scalar, always 0) — ignored
    const int*   ei = (const int*)d_in[4];
    const float* ew = (const float*)d_in[5];

    int n = in_sizes[0] / FD;
    int e = in_sizes[4] / 2;
    const int* src = ei;
    const int* dst = ei + e;

    if (g_s2 == nullptr) {
        cudaStreamCreateWithFlags(&g_s2, cudaStreamNonBlocking);
        cudaEventCreateWithFlags(&g_evFork, cudaEventDisableTiming);
        cudaEventCreateWithFlags(&g_evJoin, cudaEventDisableTiming);
    }

    // fork: GEMM runs on g_s2 concurrently with the edge/CSR pipeline
    cudaEventRecord(g_evFork, 0);
    cudaStreamWaitEvent(g_s2, g_evFork, 0);
    k_gemm<<<(n + BM - 1) / BM, 256, 0, g_s2>>>(x, W, n);
    cudaEventRecord(g_evJoin, g_s2);

    // edge / CSR pipeline (g_acc/g_total/g_done zero by invariant)
    int e4 = (e + 1023) / 1024;          // blocks of 256 threads x 4 edges
    k_deg  <<<e4, 256>>>(dst, ew, e);

    int nb = (n + 1023) / 1024;
    k_scan <<<nb, 1024>>>(n, nb);

    k_place<<<e4, 256>>>(src, dst, ew, e);

    // join: gather needs both h and the CSR
    cudaStreamWaitEvent(0, g_evJoin, 0);
    k_gather<<<(n * 32 + 255) / 256, 256>>>(b, (float*)d_out, n);
}